// round 11
// baseline (speedup 1.0000x reference)
#include <cuda_runtime.h>
#include <math.h>
#include <stdint.h>

// Shapes
#define DIMC 192
#define HW   1024
#define BATCH 32
#define GRAMD 18528   // 192*193/2
#define N1 9264
#define N2 4632
#define N3 64

// Scratch (device globals: no allocation allowed in kernel_launch)
__device__ float g_buf[BATCH * GRAMD];
__device__ float h1_buf[BATCH * N1];
__device__ float h2_buf[BATCH * N2];
__device__ float h3p_buf[4 * BATCH * N3];   // split-K partials for layer 3

// ---------------------------------------------------------------------------
// helpers
// ---------------------------------------------------------------------------
__device__ __forceinline__ void ffma2(unsigned long long& d,
                                      unsigned long long a,
                                      unsigned long long b)
{
    asm("fma.rn.f32x2 %0, %1, %2, %0;" : "+l"(d) : "l"(a), "l"(b));
}

__device__ __forceinline__ float fold_f32x2(unsigned long long v)
{
    float2 f = *reinterpret_cast<float2*>(&v);
    return f.x + f.y;
}

__device__ __forceinline__ void cp_async16(uint32_t smem_addr, const void* gptr)
{
    asm volatile("cp.async.ca.shared.global [%0], [%1], 16;"
                 :: "r"(smem_addr), "l"(gptr));
}

__device__ __forceinline__ void mma_tf32(float* d, const uint32_t* a,
                                         uint32_t b0, uint32_t b1)
{
    asm volatile(
        "mma.sync.aligned.m16n8k8.row.col.f32.tf32.tf32.f32 "
        "{%0,%1,%2,%3}, {%4,%5,%6,%7}, {%8,%9}, {%0,%1,%2,%3};"
        : "+f"(d[0]), "+f"(d[1]), "+f"(d[2]), "+f"(d[3])
        : "r"(a[0]), "r"(a[1]), "r"(a[2]), "r"(a[3]), "r"(b0), "r"(b1));
}

// ---------------------------------------------------------------------------
// Kernel 1: per-sample Gram upper-triangle features (f32x2 inner loop; proven).
// ---------------------------------------------------------------------------
__global__ void gram_kernel(const float* __restrict__ x, float* __restrict__ g)
{
    __shared__ float As[64][18];
    __shared__ float Bs[64][18];

    const int TI[6] = {0, 0, 0, 1, 1, 2};
    const int TJ[6] = {0, 1, 2, 1, 2, 2};

    int pair = blockIdx.x;
    int b    = blockIdx.y;
    int ti = TI[pair], tj = TJ[pair];

    const float* feat = x + (size_t)b * DIMC * HW;

    int t  = threadIdx.x;
    int ty = t >> 4;
    int tx = t & 15;

    unsigned long long acc[4][4];
    #pragma unroll
    for (int i = 0; i < 4; i++)
        #pragma unroll
        for (int j = 0; j < 4; j++) acc[i][j] = 0ull;

    for (int k0 = 0; k0 < HW; k0 += 16) {
        #pragma unroll
        for (int l = 0; l < 4; l++) {
            int idx = t + l * 256;
            int row = idx >> 4;
            int col = idx & 15;
            As[row][col] = feat[(size_t)(ti * 64 + row) * HW + k0 + col];
            Bs[row][col] = feat[(size_t)(tj * 64 + row) * HW + k0 + col];
        }
        __syncthreads();

        #pragma unroll
        for (int kk = 0; kk < 16; kk += 2) {
            unsigned long long a2[4], b2[4];
            #pragma unroll
            for (int i = 0; i < 4; i++)
                a2[i] = *reinterpret_cast<const unsigned long long*>(&As[ty * 4 + i][kk]);
            #pragma unroll
            for (int j = 0; j < 4; j++)
                b2[j] = *reinterpret_cast<const unsigned long long*>(&Bs[tx * 4 + j][kk]);
            #pragma unroll
            for (int i = 0; i < 4; i++)
                #pragma unroll
                for (int j = 0; j < 4; j++)
                    ffma2(acc[i][j], a2[i], b2[j]);
        }
        __syncthreads();
    }

    #pragma unroll
    for (int i = 0; i < 4; i++) {
        int gi = ti * 64 + ty * 4 + i;
        #pragma unroll
        for (int j = 0; j < 4; j++) {
            int gj = tj * 64 + tx * 4 + j;
            if (gi <= gj) {
                int off = gi * DIMC - (gi * (gi - 1)) / 2 + (gj - gi);
                g[(size_t)b * GRAMD + off] = fold_f32x2(acc[i][j]);
            }
        }
    }
}

// ---------------------------------------------------------------------------
// TF32 tensor-core GEMM + bias + leaky-relu.  out[b][n], b = 0..31.
// Block = 256 threads = 8 warps; triple-buffered cp.async, KC = 48.
// k-permutation trick: mma slot (tig, lo/hi) of step j takes logical
// k = tig*12 + 2j + hi (same permutation on A and B -> dot product exact).
// Each thread therefore loads 12 CONTIGUOUS floats per fragment row with
// 3x LDS.128; no per-element LDS, no cvt (HMMA.TF32 truncates f32 bits).
// ---------------------------------------------------------------------------
template <int K, int N, int MTILE>
__global__ __launch_bounds__(256)
void gemm_mma(const float* __restrict__ in, const float* __restrict__ W,
              const float* __restrict__ bias, float* __restrict__ out)
{
    constexpr int KC    = 48;
    constexpr int PITCH = 52;            // 4-way bank-quad spread for LDS.128
    constexpr int NCH   = K / KC;        // exact for all layers (K % 48 == 0)
    constexpr int NBT   = (MTILE == 64) ? 2 : 1;
    constexpr int WF4   = MTILE * 12;
    constexpr int WRND  = (WF4 + 255) / 256;

    __shared__ float Ws[3][MTILE * PITCH];
    __shared__ float Gs[3][32 * PITCH];

    int tid  = threadIdx.x;
    int lane = tid & 31;
    int warp = tid >> 5;                 // 0..7
    int gid  = lane >> 2;                // 0..7
    int tig  = lane & 3;                 // 0..3
    int n0b  = blockIdx.x * MTILE;

    int nw, bbase;
    if (MTILE == 64) { nw = (warp >> 1) * 16; bbase = (warp & 1) * 16; }
    else             { nw = (warp & 1) * 16;  bbase = (warp >> 1) * 8; }

    float d[NBT][4];
    #pragma unroll
    for (int bt = 0; bt < NBT; bt++)
        #pragma unroll
        for (int r = 0; r < 4; r++) d[bt][r] = 0.0f;

    uint32_t ws_base[3], gs_base[3];
    #pragma unroll
    for (int s = 0; s < 3; s++) {
        ws_base[s] = (uint32_t)__cvta_generic_to_shared(&Ws[s][0]);
        gs_base[s] = (uint32_t)__cvta_generic_to_shared(&Gs[s][0]);
    }

    auto issue = [&](int c) {
        int k0 = c * KC;
        int s  = c % 3;
        #pragma unroll
        for (int r = 0; r < WRND; r++) {
            int f = tid + r * 256;
            if (f < WF4) {
                int row = f / 12;
                int q   = f % 12;
                int grow = n0b + row;
                if (grow >= N) grow = N - 1;        // safe duplicate; stores guarded
                cp_async16(ws_base[s] + (uint32_t)(row * PITCH + q * 4) * 4,
                           W + (size_t)grow * K + k0 + q * 4);
            }
        }
        #pragma unroll
        for (int r = 0; r < 2; r++) {
            int f = tid + r * 256;
            if (f < 384) {
                int row = f / 12;
                int q   = f % 12;
                cp_async16(gs_base[s] + (uint32_t)(row * PITCH + q * 4) * 4,
                           in + (size_t)row * K + k0 + q * 4);
            }
        }
        asm volatile("cp.async.commit_group;");
    };

    issue(0);
    if (NCH > 1) issue(1);
    if (NCH > 2) issue(2);

    const int acol = tig * 12;

    for (int c = 0; c < NCH; c++) {
        asm volatile("cp.async.wait_group 2;");
        __syncthreads();

        int s = c % 3;
        const float* ws = &Ws[s][0];
        const float* gs = &Gs[s][0];

        // Load this thread's 12 contiguous k-values per fragment row.
        uint32_t au[2][12];
        uint32_t bu[NBT][12];
        #pragma unroll
        for (int r = 0; r < 3; r++) {
            float4 v0 = *reinterpret_cast<const float4*>(ws + (nw + gid) * PITCH + acol + r * 4);
            float4 v1 = *reinterpret_cast<const float4*>(ws + (nw + gid + 8) * PITCH + acol + r * 4);
            au[0][r*4+0] = __float_as_uint(v0.x); au[0][r*4+1] = __float_as_uint(v0.y);
            au[0][r*4+2] = __float_as_uint(v0.z); au[0][r*4+3] = __float_as_uint(v0.w);
            au[1][r*4+0] = __float_as_uint(v1.x); au[1][r*4+1] = __float_as_uint(v1.y);
            au[1][r*4+2] = __float_as_uint(v1.z); au[1][r*4+3] = __float_as_uint(v1.w);
        }
        #pragma unroll
        for (int bt = 0; bt < NBT; bt++) {
            #pragma unroll
            for (int r = 0; r < 3; r++) {
                float4 v = *reinterpret_cast<const float4*>(
                    gs + (bbase + bt * 8 + gid) * PITCH + acol + r * 4);
                bu[bt][r*4+0] = __float_as_uint(v.x); bu[bt][r*4+1] = __float_as_uint(v.y);
                bu[bt][r*4+2] = __float_as_uint(v.z); bu[bt][r*4+3] = __float_as_uint(v.w);
            }
        }

        #pragma unroll
        for (int j = 0; j < 6; j++) {
            uint32_t a[4] = { au[0][2*j], au[1][2*j], au[0][2*j+1], au[1][2*j+1] };
            #pragma unroll
            for (int bt = 0; bt < NBT; bt++)
                mma_tf32(d[bt], a, bu[bt][2*j], bu[bt][2*j+1]);
        }

        __syncthreads();
        if (c + 3 < NCH) issue(c + 3);
    }

    // Epilogue: c0=(gid,2tig) c1=(gid,2tig+1) c2=(gid+8,2tig) c3=(gid+8,2tig+1)
    #pragma unroll
    for (int bt = 0; bt < NBT; bt++) {
        int b   = bbase + bt * 8 + 2 * tig;
        int n_0 = n0b + nw + gid;
        int n_1 = n_0 + 8;
        if (n_0 < N) {
            float bi = bias[n_0];
            float v0 = d[bt][0] + bi; v0 = (v0 > 0.f) ? v0 : 0.01f * v0;
            float v1 = d[bt][1] + bi; v1 = (v1 > 0.f) ? v1 : 0.01f * v1;
            out[(size_t)b * N + n_0]       = v0;
            out[(size_t)(b + 1) * N + n_0] = v1;
        }
        if (n_1 < N) {
            float bi = bias[n_1];
            float v2 = d[bt][2] + bi; v2 = (v2 > 0.f) ? v2 : 0.01f * v2;
            float v3 = d[bt][3] + bi; v3 = (v3 > 0.f) ? v3 : 0.01f * v3;
            out[(size_t)b * N + n_1]       = v2;
            out[(size_t)(b + 1) * N + n_1] = v3;
        }
    }
}

// ---------------------------------------------------------------------------
// Layer 3, split-K partials: grid (4 kslices, 64 n), block 256 (8 warps x 4 b).
// ---------------------------------------------------------------------------
#define N2_F4 (N2 / 4)   // 1158
__global__ __launch_bounds__(256)
void gemm3_partial(const float* __restrict__ in, const float* __restrict__ W,
                   float* __restrict__ part)
{
    int ks   = blockIdx.x;
    int n    = blockIdx.y;
    int lane = threadIdx.x & 31;
    int warp = threadIdx.x >> 5;

    int k4b = ks * 290;
    int k4e = min(N2_F4, k4b + 290);

    const float4* wrow = reinterpret_cast<const float4*>(W + (size_t)n * N2);

    float acc[4] = {0.f, 0.f, 0.f, 0.f};

    for (int i = k4b + lane; i < k4e; i += 32) {
        float4 w = wrow[i];
        #pragma unroll
        for (int j = 0; j < 4; j++) {
            float4 gv = reinterpret_cast<const float4*>(in + (size_t)(warp * 4 + j) * N2)[i];
            acc[j] += w.x * gv.x + w.y * gv.y + w.z * gv.z + w.w * gv.w;
        }
    }

    #pragma unroll
    for (int off = 16; off > 0; off >>= 1)
        #pragma unroll
        for (int j = 0; j < 4; j++)
            acc[j] += __shfl_xor_sync(0xffffffffu, acc[j], off);

    if (lane == 0) {
        #pragma unroll
        for (int j = 0; j < 4; j++)
            part[((size_t)ks * BATCH + warp * 4 + j) * N3 + n] = acc[j];
    }
}

// ---------------------------------------------------------------------------
// Final: reduce split-K partials, + b3, leaky-relu, L2-normalize, dot W4,
// + b4, sigmoid.
// ---------------------------------------------------------------------------
__global__ void final_kernel(const float* __restrict__ part,
                             const float* __restrict__ b3,
                             const float* __restrict__ W4,
                             const float* __restrict__ b4,
                             float* __restrict__ out)
{
    int b    = threadIdx.x >> 5;
    int lane = threadIdx.x & 31;
    int i0 = lane * 2, i1 = lane * 2 + 1;

    float v0 = b3[i0], v1 = b3[i1];
    #pragma unroll
    for (int s = 0; s < 4; s++) {
        v0 += part[((size_t)s * BATCH + b) * N3 + i0];
        v1 += part[((size_t)s * BATCH + b) * N3 + i1];
    }
    v0 = (v0 > 0.f) ? v0 : 0.01f * v0;
    v1 = (v1 > 0.f) ? v1 : 0.01f * v1;

    float ss = v0 * v0 + v1 * v1;
    #pragma unroll
    for (int off = 16; off > 0; off >>= 1)
        ss += __shfl_xor_sync(0xffffffffu, ss, off);

    float denom = fmaxf(sqrtf(ss), 1e-12f);

    float dsum = v0 * W4[i0] + v1 * W4[i1];
    #pragma unroll
    for (int off = 16; off > 0; off >>= 1)
        dsum += __shfl_xor_sync(0xffffffffu, dsum, off);

    if (lane == 0) {
        float logit = dsum / denom + b4[0];
        out[b] = 1.0f / (1.0f + expf(-logit));
    }
}

// ---------------------------------------------------------------------------
// Launch.  Inputs (metadata order): x, W1, b1, W2, b2, W3, b3, W4, b4 (fp32)
// ---------------------------------------------------------------------------
extern "C" void kernel_launch(void* const* d_in, const int* in_sizes, int n_in,
                              void* d_out, int out_size)
{
    const float* x  = (const float*)d_in[0];
    const float* W1 = (const float*)d_in[1];
    const float* b1 = (const float*)d_in[2];
    const float* W2 = (const float*)d_in[3];
    const float* b2 = (const float*)d_in[4];
    const float* W3 = (const float*)d_in[5];
    const float* b3 = (const float*)d_in[6];
    const float* W4 = (const float*)d_in[7];
    const float* b4 = (const float*)d_in[8];
    float* out = (float*)d_out;

    float *g, *h1, *h2, *h3p;
    cudaGetSymbolAddress((void**)&g,   g_buf);
    cudaGetSymbolAddress((void**)&h1,  h1_buf);
    cudaGetSymbolAddress((void**)&h2,  h2_buf);
    cudaGetSymbolAddress((void**)&h3p, h3p_buf);

    gram_kernel<<<dim3(6, BATCH), 256>>>(x, g);

    gemm_mma<GRAMD, N1, 64><<<(N1 + 63) / 64, 256>>>(g,  W1, b1, h1);  // 145 blocks
    gemm_mma<N1,    N2, 32><<<(N2 + 31) / 32, 256>>>(h1, W2, b2, h2);  // 145 blocks

    gemm3_partial<<<dim3(4, N3), 256>>>(h2, W3, h3p);
    final_kernel<<<1, 1024>>>(h3p, b3, W4, b4, out);
}

// round 12
// speedup vs baseline: 1.4881x; 1.4881x over previous
#include <cuda_runtime.h>
#include <math.h>
#include <stdint.h>

// Shapes
#define DIMC 192
#define HW   1024
#define BATCH 32
#define GRAMD 18528   // 192*193/2
#define N1 9264
#define N2 4632
#define N3 64

// Scratch (device globals: no allocation allowed in kernel_launch)
__device__ float g_buf[BATCH * GRAMD];
__device__ float h1_buf[BATCH * N1];
__device__ float h2_buf[BATCH * N2];
__device__ float h3p_buf[4 * BATCH * N3];   // split-K partials for layer 3

// ---------------------------------------------------------------------------
// helpers
// ---------------------------------------------------------------------------
__device__ __forceinline__ void ffma2(unsigned long long& d,
                                      unsigned long long a,
                                      unsigned long long b)
{
    asm("fma.rn.f32x2 %0, %1, %2, %0;" : "+l"(d) : "l"(a), "l"(b));
}

__device__ __forceinline__ float fold_f32x2(unsigned long long v)
{
    float2 f = *reinterpret_cast<float2*>(&v);
    return f.x + f.y;
}

__device__ __forceinline__ void cp_async16(uint32_t smem_addr, const void* gptr)
{
    asm volatile("cp.async.ca.shared.global [%0], [%1], 16;"
                 :: "r"(smem_addr), "l"(gptr));
}

__device__ __forceinline__ void mma_tf32(float* d, uint32_t a0, uint32_t a1,
                                         uint32_t a2, uint32_t a3,
                                         uint32_t b0, uint32_t b1)
{
    asm volatile(
        "mma.sync.aligned.m16n8k8.row.col.f32.tf32.tf32.f32 "
        "{%0,%1,%2,%3}, {%4,%5,%6,%7}, {%8,%9}, {%0,%1,%2,%3};"
        : "+f"(d[0]), "+f"(d[1]), "+f"(d[2]), "+f"(d[3])
        : "r"(a0), "r"(a1), "r"(a2), "r"(a3), "r"(b0), "r"(b1));
}

// ---------------------------------------------------------------------------
// Kernel 1: per-sample Gram upper-triangle features (f32x2 inner loop; proven).
// ---------------------------------------------------------------------------
__global__ void gram_kernel(const float* __restrict__ x, float* __restrict__ g)
{
    __shared__ float As[64][18];
    __shared__ float Bs[64][18];

    const int TI[6] = {0, 0, 0, 1, 1, 2};
    const int TJ[6] = {0, 1, 2, 1, 2, 2};

    int pair = blockIdx.x;
    int b    = blockIdx.y;
    int ti = TI[pair], tj = TJ[pair];

    const float* feat = x + (size_t)b * DIMC * HW;

    int t  = threadIdx.x;
    int ty = t >> 4;
    int tx = t & 15;

    unsigned long long acc[4][4];
    #pragma unroll
    for (int i = 0; i < 4; i++)
        #pragma unroll
        for (int j = 0; j < 4; j++) acc[i][j] = 0ull;

    for (int k0 = 0; k0 < HW; k0 += 16) {
        #pragma unroll
        for (int l = 0; l < 4; l++) {
            int idx = t + l * 256;
            int row = idx >> 4;
            int col = idx & 15;
            As[row][col] = feat[(size_t)(ti * 64 + row) * HW + k0 + col];
            Bs[row][col] = feat[(size_t)(tj * 64 + row) * HW + k0 + col];
        }
        __syncthreads();

        #pragma unroll
        for (int kk = 0; kk < 16; kk += 2) {
            unsigned long long a2[4], b2[4];
            #pragma unroll
            for (int i = 0; i < 4; i++)
                a2[i] = *reinterpret_cast<const unsigned long long*>(&As[ty * 4 + i][kk]);
            #pragma unroll
            for (int j = 0; j < 4; j++)
                b2[j] = *reinterpret_cast<const unsigned long long*>(&Bs[tx * 4 + j][kk]);
            #pragma unroll
            for (int i = 0; i < 4; i++)
                #pragma unroll
                for (int j = 0; j < 4; j++)
                    ffma2(acc[i][j], a2[i], b2[j]);
        }
        __syncthreads();
    }

    #pragma unroll
    for (int i = 0; i < 4; i++) {
        int gi = ti * 64 + ty * 4 + i;
        #pragma unroll
        for (int j = 0; j < 4; j++) {
            int gj = tj * 64 + tx * 4 + j;
            if (gi <= gj) {
                int off = gi * DIMC - (gi * (gi - 1)) / 2 + (gj - gi);
                g[(size_t)b * GRAMD + off] = fold_f32x2(acc[i][j]);
            }
        }
    }
}

// ---------------------------------------------------------------------------
// TF32 tensor-core GEMM + bias + leaky-relu.  out[b][n], b = 0..31.
// Block = 256 threads = 8 warps; triple-buffered cp.async, KC = 48.
// k-permutation: mma slot (tig, lo/hi) of step j takes logical
// k = tig*12 + 2j + hi (same permutation on A and B -> dot product exact;
// verified R11, rel_err 4.8e-6). Raw f32 bits feed HMMA.TF32 (no cvt).
// Fragments staged in 3 interleaved groups of float4s -> 12 LDS.128 + 12 MMA
// per warp-chunk, <=16 live fragment regs (fixes R11's spill regression).
// ---------------------------------------------------------------------------
template <int K, int N, int MTILE>
__global__ __launch_bounds__(256)
void gemm_mma(const float* __restrict__ in, const float* __restrict__ W,
              const float* __restrict__ bias, float* __restrict__ out)
{
    constexpr int KC    = 48;
    constexpr int PITCH = 52;
    constexpr int NCH   = K / KC;        // exact for all layers (K % 48 == 0)
    constexpr int NBT   = (MTILE == 64) ? 2 : 1;
    constexpr int WF4   = MTILE * 12;
    constexpr int WRND  = (WF4 + 255) / 256;

    __shared__ float Ws[3][MTILE * PITCH];
    __shared__ float Gs[3][32 * PITCH];

    int tid  = threadIdx.x;
    int lane = tid & 31;
    int warp = tid >> 5;                 // 0..7
    int gid  = lane >> 2;                // 0..7
    int tig  = lane & 3;                 // 0..3
    int n0b  = blockIdx.x * MTILE;

    int nw, bbase;
    if (MTILE == 64) { nw = (warp >> 1) * 16; bbase = (warp & 1) * 16; }
    else             { nw = (warp & 1) * 16;  bbase = (warp >> 1) * 8; }

    float d[NBT][4];
    #pragma unroll
    for (int bt = 0; bt < NBT; bt++)
        #pragma unroll
        for (int r = 0; r < 4; r++) d[bt][r] = 0.0f;

    uint32_t ws_base[3], gs_base[3];
    #pragma unroll
    for (int s = 0; s < 3; s++) {
        ws_base[s] = (uint32_t)__cvta_generic_to_shared(&Ws[s][0]);
        gs_base[s] = (uint32_t)__cvta_generic_to_shared(&Gs[s][0]);
    }

    auto issue = [&](int c) {
        int k0 = c * KC;
        int s  = c % 3;
        #pragma unroll
        for (int r = 0; r < WRND; r++) {
            int f = tid + r * 256;
            if (f < WF4) {
                int row = f / 12;
                int q   = f % 12;
                int grow = n0b + row;
                if (grow >= N) grow = N - 1;        // safe duplicate; stores guarded
                cp_async16(ws_base[s] + (uint32_t)(row * PITCH + q * 4) * 4,
                           W + (size_t)grow * K + k0 + q * 4);
            }
        }
        #pragma unroll
        for (int r = 0; r < 2; r++) {
            int f = tid + r * 256;
            if (f < 384) {
                int row = f / 12;
                int q   = f % 12;
                cp_async16(gs_base[s] + (uint32_t)(row * PITCH + q * 4) * 4,
                           in + (size_t)row * K + k0 + q * 4);
            }
        }
        asm volatile("cp.async.commit_group;");
    };

    issue(0);
    if (NCH > 1) issue(1);
    if (NCH > 2) issue(2);

    const int acol = tig * 12;

    for (int c = 0; c < NCH; c++) {
        asm volatile("cp.async.wait_group 2;");
        __syncthreads();

        int s = c % 3;
        const float* ws = &Ws[s][0];
        const float* gs = &Gs[s][0];

        // 3 interleaved groups: each covers mma steps j = 2r, 2r+1.
        #pragma unroll
        for (int r = 0; r < 3; r++) {
            float4 a0 = *reinterpret_cast<const float4*>(ws + (nw + gid) * PITCH + acol + r * 4);
            float4 a1 = *reinterpret_cast<const float4*>(ws + (nw + gid + 8) * PITCH + acol + r * 4);
            #pragma unroll
            for (int bt = 0; bt < NBT; bt++) {
                float4 bv = *reinterpret_cast<const float4*>(
                    gs + (bbase + bt * 8 + gid) * PITCH + acol + r * 4);
                // step j = 2r  : A slots (lo=.x/.y pair) -> {a0.x,a1.x,a0.y,a1.y}
                mma_tf32(d[bt],
                         __float_as_uint(a0.x), __float_as_uint(a1.x),
                         __float_as_uint(a0.y), __float_as_uint(a1.y),
                         __float_as_uint(bv.x), __float_as_uint(bv.y));
                // step j = 2r+1: {a0.z,a1.z,a0.w,a1.w}
                mma_tf32(d[bt],
                         __float_as_uint(a0.z), __float_as_uint(a1.z),
                         __float_as_uint(a0.w), __float_as_uint(a1.w),
                         __float_as_uint(bv.z), __float_as_uint(bv.w));
            }
        }

        __syncthreads();
        if (c + 3 < NCH) issue(c + 3);
    }

    // Epilogue: c0=(gid,2tig) c1=(gid,2tig+1) c2=(gid+8,2tig) c3=(gid+8,2tig+1)
    #pragma unroll
    for (int bt = 0; bt < NBT; bt++) {
        int b   = bbase + bt * 8 + 2 * tig;
        int n_0 = n0b + nw + gid;
        int n_1 = n_0 + 8;
        if (n_0 < N) {
            float bi = bias[n_0];
            float v0 = d[bt][0] + bi; v0 = (v0 > 0.f) ? v0 : 0.01f * v0;
            float v1 = d[bt][1] + bi; v1 = (v1 > 0.f) ? v1 : 0.01f * v1;
            out[(size_t)b * N + n_0]       = v0;
            out[(size_t)(b + 1) * N + n_0] = v1;
        }
        if (n_1 < N) {
            float bi = bias[n_1];
            float v2 = d[bt][2] + bi; v2 = (v2 > 0.f) ? v2 : 0.01f * v2;
            float v3 = d[bt][3] + bi; v3 = (v3 > 0.f) ? v3 : 0.01f * v3;
            out[(size_t)b * N + n_1]       = v2;
            out[(size_t)(b + 1) * N + n_1] = v3;
        }
    }
}

// ---------------------------------------------------------------------------
// Layer 3, split-K partials: grid (4 kslices, 64 n), block 256 (8 warps x 4 b).
// ---------------------------------------------------------------------------
#define N2_F4 (N2 / 4)   // 1158
__global__ __launch_bounds__(256)
void gemm3_partial(const float* __restrict__ in, const float* __restrict__ W,
                   float* __restrict__ part)
{
    int ks   = blockIdx.x;
    int n    = blockIdx.y;
    int lane = threadIdx.x & 31;
    int warp = threadIdx.x >> 5;

    int k4b = ks * 290;
    int k4e = min(N2_F4, k4b + 290);

    const float4* wrow = reinterpret_cast<const float4*>(W + (size_t)n * N2);

    float acc[4] = {0.f, 0.f, 0.f, 0.f};

    for (int i = k4b + lane; i < k4e; i += 32) {
        float4 w = wrow[i];
        #pragma unroll
        for (int j = 0; j < 4; j++) {
            float4 gv = reinterpret_cast<const float4*>(in + (size_t)(warp * 4 + j) * N2)[i];
            acc[j] += w.x * gv.x + w.y * gv.y + w.z * gv.z + w.w * gv.w;
        }
    }

    #pragma unroll
    for (int off = 16; off > 0; off >>= 1)
        #pragma unroll
        for (int j = 0; j < 4; j++)
            acc[j] += __shfl_xor_sync(0xffffffffu, acc[j], off);

    if (lane == 0) {
        #pragma unroll
        for (int j = 0; j < 4; j++)
            part[((size_t)ks * BATCH + warp * 4 + j) * N3 + n] = acc[j];
    }
}

// ---------------------------------------------------------------------------
// Final: reduce split-K partials, + b3, leaky-relu, L2-normalize, dot W4,
// + b4, sigmoid.
// ---------------------------------------------------------------------------
__global__ void final_kernel(const float* __restrict__ part,
                             const float* __restrict__ b3,
                             const float* __restrict__ W4,
                             const float* __restrict__ b4,
                             float* __restrict__ out)
{
    int b    = threadIdx.x >> 5;
    int lane = threadIdx.x & 31;
    int i0 = lane * 2, i1 = lane * 2 + 1;

    float v0 = b3[i0], v1 = b3[i1];
    #pragma unroll
    for (int s = 0; s < 4; s++) {
        v0 += part[((size_t)s * BATCH + b) * N3 + i0];
        v1 += part[((size_t)s * BATCH + b) * N3 + i1];
    }
    v0 = (v0 > 0.f) ? v0 : 0.01f * v0;
    v1 = (v1 > 0.f) ? v1 : 0.01f * v1;

    float ss = v0 * v0 + v1 * v1;
    #pragma unroll
    for (int off = 16; off > 0; off >>= 1)
        ss += __shfl_xor_sync(0xffffffffu, ss, off);

    float denom = fmaxf(sqrtf(ss), 1e-12f);

    float dsum = v0 * W4[i0] + v1 * W4[i1];
    #pragma unroll
    for (int off = 16; off > 0; off >>= 1)
        dsum += __shfl_xor_sync(0xffffffffu, dsum, off);

    if (lane == 0) {
        float logit = dsum / denom + b4[0];
        out[b] = 1.0f / (1.0f + expf(-logit));
    }
}

// ---------------------------------------------------------------------------
// Launch.  Inputs (metadata order): x, W1, b1, W2, b2, W3, b3, W4, b4 (fp32)
// ---------------------------------------------------------------------------
extern "C" void kernel_launch(void* const* d_in, const int* in_sizes, int n_in,
                              void* d_out, int out_size)
{
    const float* x  = (const float*)d_in[0];
    const float* W1 = (const float*)d_in[1];
    const float* b1 = (const float*)d_in[2];
    const float* W2 = (const float*)d_in[3];
    const float* b2 = (const float*)d_in[4];
    const float* W3 = (const float*)d_in[5];
    const float* b3 = (const float*)d_in[6];
    const float* W4 = (const float*)d_in[7];
    const float* b4 = (const float*)d_in[8];
    float* out = (float*)d_out;

    float *g, *h1, *h2, *h3p;
    cudaGetSymbolAddress((void**)&g,   g_buf);
    cudaGetSymbolAddress((void**)&h1,  h1_buf);
    cudaGetSymbolAddress((void**)&h2,  h2_buf);
    cudaGetSymbolAddress((void**)&h3p, h3p_buf);

    gram_kernel<<<dim3(6, BATCH), 256>>>(x, g);

    gemm_mma<GRAMD, N1, 64><<<(N1 + 63) / 64, 256>>>(g,  W1, b1, h1);  // 145 blocks
    gemm_mma<N1,    N2, 32><<<(N2 + 31) / 32, 256>>>(h1, W2, b2, h2);  // 145 blocks

    gemm3_partial<<<dim3(4, N3), 256>>>(h2, W3, h3p);
    final_kernel<<<1, 1024>>>(h3p, b3, W4, b4, out);
}